// round 1
// baseline (speedup 1.0000x reference)
#include <cuda_runtime.h>

#define B_   64
#define T_   2048
#define DZ_  512
#define DC_  256
#define K_   12
#define R_   2
#define KO_  (K_ * DZ_)   // 6144

#define TBT_ 128          // t'-tile per score block
#define DK_  32           // d-chunk per smem stage

// ---- scratch (static device allocations; no cudaMalloc allowed) ----
__device__ __align__(16) float g_pred[B_ * KO_];        // [b][k*Dz+o]   1.5 MB
__device__ __align__(16) float g_s[K_ * B_ * T_];       // [k][b][t']    6.3 MB
__device__ float g_partial[K_ * B_];

// ============================================================================
// Kernel A: pred[b][ko] = sum_d c[b, t[b], d] * W[ko][d] + bias[ko]
// GEMM 64 x 6144 x 256, tiled so W is read once total.
// grid = 96 blocks (64 ko-rows each), 256 threads = 16(ko) x 16(b) micro 4x4.
// ============================================================================
__global__ void pred_kernel(const float* __restrict__ c,
                            const float* __restrict__ W,
                            const float* __restrict__ bias,
                            const int*   __restrict__ t) {
    __shared__ float cts[64][65];
    __shared__ float ws [64][65];
    __shared__ int   ts[B_];

    int tid = threadIdx.x;
    if (tid < B_) ts[tid] = t[tid];
    __syncthreads();

    int ko0 = blockIdx.x * 64;
    int tx = tid & 15, ty = tid >> 4;
    float acc[4][4] = {};

    for (int d0 = 0; d0 < DC_; d0 += 64) {
        #pragma unroll
        for (int i = 0; i < 16; i++) {
            int f = tid + i * 256;
            int r = f >> 6, dd = f & 63;
            cts[r][dd] = c[((long)r * T_ + ts[r]) * DC_ + d0 + dd];
            ws [r][dd] = W[(long)(ko0 + r) * DC_ + d0 + dd];
        }
        __syncthreads();
        #pragma unroll 8
        for (int d = 0; d < 64; d++) {
            float cv[4], wv[4];
            #pragma unroll
            for (int i = 0; i < 4; i++) cv[i] = cts[ty * 4 + i][d];
            #pragma unroll
            for (int j = 0; j < 4; j++) wv[j] = ws[tx * 4 + j][d];
            #pragma unroll
            for (int i = 0; i < 4; i++)
                #pragma unroll
                for (int j = 0; j < 4; j++) acc[i][j] += cv[i] * wv[j];
        }
        __syncthreads();
    }

    #pragma unroll
    for (int i = 0; i < 4; i++) {
        int b = ty * 4 + i;
        #pragma unroll
        for (int j = 0; j < 4; j++) {
            int ko = ko0 + tx * 4 + j;
            g_pred[(long)b * KO_ + ko] = acc[i][j] + bias[ko];
        }
    }
}

// ============================================================================
// Kernel B (the hot one): s[k][b][t'] = dot(z[b,t',:], pred[b,k,:])
// HBM-bound: streams 268 MB of z exactly once. FFMA2 (fma.rn.f32x2) packs
// 2 fp32 FMAs/instr so FP32 issue stays under the memory floor.
// grid = (T/128, B) = 1024 blocks, 128 threads, 1 t'-row x 12 k per thread.
// ============================================================================
__global__ __launch_bounds__(128) void score_kernel(const float* __restrict__ z) {
    __shared__ __align__(16) float preds[KO_];       // 24 KB, this b's 12 pred vecs
    __shared__ float zs[TBT_][DK_ + 2];              // pad 34 -> conflict-free LDS.64

    int tid = threadIdx.x;
    int b   = blockIdx.y;
    int t0  = blockIdx.x * TBT_;

    // stage pred[b] (broadcast-read later)
    const float4* gp = (const float4*)(g_pred + (long)b * KO_);
    float4* sp = (float4*)preds;
    #pragma unroll
    for (int i = 0; i < KO_ / 4 / 128; i++) sp[tid + i * 128] = gp[tid + i * 128];

    unsigned long long acc[K_];
    #pragma unroll
    for (int k = 0; k < K_; k++) acc[k] = 0ULL;

    __syncthreads();

    const float* zb = z + ((long)b * T_ + t0) * DZ_;

    for (int d0 = 0; d0 < DZ_; d0 += DK_) {
        // stage z tile 128 x 32, fully coalesced 16B loads
        #pragma unroll
        for (int i = 0; i < 8; i++) {
            int f4 = tid + i * 128;
            int r = f4 >> 3, cc = f4 & 7;
            float4 v = *(const float4*)(zb + (long)r * DZ_ + d0 + cc * 4);
            float* dst = &zs[r][cc * 4];
            *(float2*)(dst)     = make_float2(v.x, v.y);
            *(float2*)(dst + 2) = make_float2(v.z, v.w);
        }
        __syncthreads();
        #pragma unroll
        for (int dd = 0; dd < DK_; dd += 2) {
            unsigned long long z2 = *(const unsigned long long*)(&zs[tid][dd]);
            #pragma unroll
            for (int k = 0; k < K_; k++) {
                unsigned long long p2 =
                    *(const unsigned long long*)(&preds[k * DZ_ + d0 + dd]);
                asm("fma.rn.f32x2 %0, %1, %2, %0;"
                    : "+l"(acc[k]) : "l"(z2), "l"(p2));
            }
        }
        __syncthreads();
    }

    #pragma unroll
    for (int k = 0; k < K_; k++) {
        float lo = __uint_as_float((unsigned)(acc[k] & 0xffffffffu));
        float hi = __uint_as_float((unsigned)(acc[k] >> 32));
        g_s[((long)k * B_ + b) * T_ + t0 + tid] = lo + hi;
    }
}

// ============================================================================
// Kernel C: per (k,b): pos + 2 replicates of 2047 sampled negatives ->
// mean logsumexp. s-row lives in smem; fixed-order tree reductions.
// grid = 768 blocks, 256 threads.
// ============================================================================
__global__ void loss_kernel(const int* __restrict__ t,
                            const int* __restrict__ ridx_g) {
    __shared__ float srow[T_];
    __shared__ float red[256];

    int tid = threadIdx.x;
    int kb  = blockIdx.x;
    int k = kb >> 6, b = kb & 63;          // kb = k*B + b

    const float* src = g_s + (long)kb * T_;
    for (int i = tid; i < T_; i += 256) srow[i] = src[i];
    __syncthreads();

    int e = t[b] + k + 1;
    float pos = srow[e];
    float lse_sum = 0.f;

    for (int r = 0; r < R_; r++) {
        const int* ridx = ridx_g + ((long)k * R_ + r) * (T_ - 1);
        float v[8];
        float m = pos;
        #pragma unroll
        for (int it = 0; it < 8; it++) {
            int i = tid + it * 256;
            float x = -3.0e38f;
            if (i < T_ - 1) {
                int j = ridx[i];
                j += (j >= e);             // skip the positive frame
                x = srow[j];
            }
            v[it] = x;
            m = fmaxf(m, x);
        }
        red[tid] = m; __syncthreads();
        for (int s = 128; s > 0; s >>= 1) {
            if (tid < s) red[tid] = fmaxf(red[tid], red[tid + s]);
            __syncthreads();
        }
        m = red[0]; __syncthreads();

        float sacc = (tid == 0) ? expf(pos - m) : 0.f;
        #pragma unroll
        for (int it = 0; it < 8; it++)
            if (tid + it * 256 < T_ - 1) sacc += expf(v[it] - m);
        red[tid] = sacc; __syncthreads();
        for (int s = 128; s > 0; s >>= 1) {
            if (tid < s) red[tid] += red[tid + s];
            __syncthreads();
        }
        lse_sum += m + logf(red[0]);
        __syncthreads();
    }

    if (tid == 0) g_partial[kb] = lse_sum / (float)R_ - pos;
}

// ============================================================================
// Kernel D: deterministic final reduce -> loss scalar
// ============================================================================
__global__ void final_kernel(float* __restrict__ out) {
    __shared__ float red[256];
    int tid = threadIdx.x;
    float s = 0.f;
    for (int i = tid; i < K_ * B_; i += 256) s += g_partial[i];
    red[tid] = s; __syncthreads();
    for (int st = 128; st > 0; st >>= 1) {
        if (tid < st) red[tid] += red[tid + st];
        __syncthreads();
    }
    if (tid == 0) out[0] = red[0] / (float)(K_ * B_);
}

// ============================================================================
extern "C" void kernel_launch(void* const* d_in, const int* in_sizes, int n_in,
                              void* d_out, int out_size) {
    const float* z        = (const float*)d_in[0];
    const float* c        = (const float*)d_in[1];
    const float* Wk_w     = (const float*)d_in[2];
    const float* Wk_b     = (const float*)d_in[3];
    const int*   t        = (const int*)d_in[4];
    const int*   rand_idx = (const int*)d_in[5];
    // d_in[6] = n_replicates (constant 2, baked in)

    pred_kernel<<<KO_ / 64, 256>>>(c, Wk_w, Wk_b, t);
    score_kernel<<<dim3(T_ / TBT_, B_), 128>>>(z);
    loss_kernel<<<K_ * B_, 256>>>(t, rand_idx);
    final_kernel<<<1, 256>>>((float*)d_out);
}

// round 2
// speedup vs baseline: 1.0577x; 1.0577x over previous
#include <cuda_runtime.h>
#include <cstdint>

#define B_   64
#define T_   2048
#define DZ_  512
#define DC_  256
#define K_   12
#define R_   2
#define KO_  (K_ * DZ_)     // 6144

// score kernel tiling
#define RPB  512            // t' rows per block
#define SDK  16             // d floats per pipeline stage
#define NSTG (DZ_ / SDK)    // 32 stages
#define P2   9              // smem pitch in float2 (odd -> conflict-free LDS.64)
#define SCORE_SMEM (KO_ * 4 + 2 * RPB * P2 * 8)   // 24576 + 73728 = 98304 B

// ---- scratch (static device allocations; no cudaMalloc allowed) ----
__device__ __align__(16) float g_pred[B_ * KO_];   // [b][k*Dz+o]
__device__ __align__(16) float g_s[K_ * B_ * T_];  // [k][b][t']
__device__ unsigned long long g_acc;               // Q32.32 fixed-point loss accum
__device__ int g_cnt;

static __device__ __forceinline__ unsigned smem_u32(const void* p) {
    return (unsigned)__cvta_generic_to_shared(p);
}

// ============================================================================
// Kernel A: pred[b][ko] = sum_d c[b, t[b], d] * W[ko][d] + bias[ko]
// GEMM 64 x 6144 x 256; W read exactly once. Also zeroes the loss accumulator.
// ============================================================================
__global__ void pred_kernel(const float* __restrict__ c,
                            const float* __restrict__ W,
                            const float* __restrict__ bias,
                            const int*   __restrict__ t) {
    __shared__ float cts[64][65];
    __shared__ float ws [64][65];
    __shared__ int   ts[B_];

    int tid = threadIdx.x;
    if (blockIdx.x == 0 && tid == 0) { g_acc = 0ULL; g_cnt = 0; }
    if (tid < B_) ts[tid] = t[tid];
    __syncthreads();

    int ko0 = blockIdx.x * 64;
    int tx = tid & 15, ty = tid >> 4;
    float acc[4][4] = {};

    for (int d0 = 0; d0 < DC_; d0 += 64) {
        #pragma unroll
        for (int i = 0; i < 16; i++) {
            int f = tid + i * 256;
            int r = f >> 6, dd = f & 63;
            cts[r][dd] = c[((long)r * T_ + ts[r]) * DC_ + d0 + dd];
            ws [r][dd] = W[(long)(ko0 + r) * DC_ + d0 + dd];
        }
        __syncthreads();
        #pragma unroll 8
        for (int d = 0; d < 64; d++) {
            float cv[4], wv[4];
            #pragma unroll
            for (int i = 0; i < 4; i++) cv[i] = cts[ty * 4 + i][d];
            #pragma unroll
            for (int j = 0; j < 4; j++) wv[j] = ws[tx * 4 + j][d];
            #pragma unroll
            for (int i = 0; i < 4; i++)
                #pragma unroll
                for (int j = 0; j < 4; j++) acc[i][j] += cv[i] * wv[j];
        }
        __syncthreads();
    }

    #pragma unroll
    for (int i = 0; i < 4; i++) {
        int b = ty * 4 + i;
        #pragma unroll
        for (int j = 0; j < 4; j++) {
            int ko = ko0 + tx * 4 + j;
            g_pred[(long)b * KO_ + ko] = acc[i][j] + bias[ko];
        }
    }
}

// ============================================================================
// Kernel B (hot): s[k][b][t'] = dot(z[b,t',:], pred[b,k,:])
// DRAM-bound design: z (268 MB) streamed once via cp.async double buffer.
// 4 rows/thread amortizes broadcast pred LDS 4x (LDS pipe ~20us < DRAM 40us).
// FFMA2 (fma.rn.f32x2) keeps FP32 issue at ~24us chip.
// grid = (T/512, B) = 256 blocks, 128 threads, 2 blocks/SM.
// ============================================================================
extern __shared__ __align__(16) float smem_dyn[];

__global__ __launch_bounds__(128) void score_kernel(const float* __restrict__ z) {
    float*  preds = smem_dyn;                      // 6144 floats
    float2* zbuf  = (float2*)(smem_dyn + KO_);     // 2 x (512*9) float2

    const int tid  = threadIdx.x;
    const int b    = blockIdx.y;
    const int t0   = blockIdx.x * RPB;
    const int l    = tid & 31, w = tid >> 5;
    const int base = w * 128;

    const float* zb = z + ((long)b * T_ + t0) * DZ_;

    auto load_stage = [&](int s, int bufsel) {
        unsigned sb = smem_u32(zbuf + bufsel * (RPB * P2));
        const float* gs = zb + s * SDK;
        #pragma unroll
        for (int j = 0; j < 32; j++) {
            int f = tid + j * 128;
            int r = f >> 3, cc = f & 7;
            unsigned sa = sb + (unsigned)((r * P2 + cc) * 8);
            const float* ga = gs + (long)r * DZ_ + cc * 2;
            asm volatile("cp.async.ca.shared.global [%0], [%1], 8;\n"
                         :: "r"(sa), "l"(ga));
        }
        asm volatile("cp.async.commit_group;\n");
    };

    // get DRAM moving first
    load_stage(0, 0);
    load_stage(1, 1);

    // stage this b's 12 pred vectors (read as warp-broadcasts later)
    const float4* gp = (const float4*)(g_pred + (long)b * KO_);
    float4* sp = (float4*)preds;
    #pragma unroll
    for (int i = 0; i < KO_ / 4 / 128; i++) sp[tid + i * 128] = gp[tid + i * 128];

    unsigned long long acc[4][K_];
    #pragma unroll
    for (int i = 0; i < 4; i++)
        #pragma unroll
        for (int k = 0; k < K_; k++) acc[i][k] = 0ULL;

    for (int s = 0; s < NSTG; s++) {
        if (s < NSTG - 1) asm volatile("cp.async.wait_group 1;\n");
        else              asm volatile("cp.async.wait_group 0;\n");
        __syncthreads();

        const float2* zc = zbuf + (s & 1) * (RPB * P2);
        const int d0 = s * SDK;
        #pragma unroll
        for (int dd = 0; dd < SDK / 2; dd++) {
            unsigned long long zz[4];
            #pragma unroll
            for (int i = 0; i < 4; i++)
                zz[i] = *(const unsigned long long*)(zc + (base + 32 * i + l) * P2 + dd);
            #pragma unroll
            for (int k = 0; k < K_; k++) {
                unsigned long long p2 =
                    *(const unsigned long long*)(preds + k * DZ_ + d0 + 2 * dd);
                #pragma unroll
                for (int i = 0; i < 4; i++)
                    asm("fma.rn.f32x2 %0, %1, %2, %0;"
                        : "+l"(acc[i][k]) : "l"(zz[i]), "l"(p2));
            }
        }
        __syncthreads();
        if (s + 2 < NSTG) load_stage(s + 2, s & 1);
    }

    #pragma unroll
    for (int i = 0; i < 4; i++) {
        int row = t0 + base + 32 * i + l;
        #pragma unroll
        for (int k = 0; k < K_; k++) {
            float lo = __uint_as_float((unsigned)(acc[i][k] & 0xffffffffu));
            float hi = __uint_as_float((unsigned)(acc[i][k] >> 32));
            g_s[((long)k * B_ + b) * T_ + row] = lo + hi;
        }
    }
}

// ============================================================================
// Kernel C: per (k,b): pos + 2 replicates of 2047 sampled negatives ->
// mean logsumexp. Warp-shuffle reductions; Q32.32 integer atomic finale
// (commutative -> deterministic), last block writes the scalar.
// grid = 768 blocks, 256 threads.
// ============================================================================
__global__ __launch_bounds__(256) void loss_kernel(const int* __restrict__ t,
                                                   const int* __restrict__ ridx_g,
                                                   float* __restrict__ out) {
    __shared__ float srow[T_];
    __shared__ float red[8];

    int tid = threadIdx.x;
    int kb  = blockIdx.x;
    int k = kb >> 6, b = kb & 63;           // kb = k*B + b
    int lane = tid & 31, wid = tid >> 5;

    const float* src = g_s + (long)kb * T_;
    for (int i = tid; i < T_; i += 256) srow[i] = src[i];
    __syncthreads();

    int e = t[b] + k + 1;
    float pos = srow[e];
    float lse_sum = 0.f;

    for (int r = 0; r < R_; r++) {
        const int* ridx = ridx_g + (k * R_ + r) * (T_ - 1);
        float v[8];
        float m = pos;
        #pragma unroll
        for (int it = 0; it < 8; it++) {
            int i = tid + it * 256;
            float x = -3.0e38f;
            if (i < T_ - 1) {
                int j = ridx[i];
                j += (j >= e);              // skip the positive frame
                x = srow[j];
            }
            v[it] = x;
            m = fmaxf(m, x);
        }
        #pragma unroll
        for (int o = 16; o; o >>= 1) m = fmaxf(m, __shfl_xor_sync(0xffffffffu, m, o));
        if (lane == 0) red[wid] = m;
        __syncthreads();
        float mm = red[0];
        #pragma unroll
        for (int j = 1; j < 8; j++) mm = fmaxf(mm, red[j]);
        __syncthreads();

        float sacc = (tid == 0) ? expf(pos - mm) : 0.f;
        #pragma unroll
        for (int it = 0; it < 8; it++)
            if (tid + it * 256 < T_ - 1) sacc += expf(v[it] - mm);
        #pragma unroll
        for (int o = 16; o; o >>= 1) sacc += __shfl_xor_sync(0xffffffffu, sacc, o);
        if (lane == 0) red[wid] = sacc;
        __syncthreads();
        float ss = red[0];
        #pragma unroll
        for (int j = 1; j < 8; j++) ss += red[j];
        __syncthreads();

        lse_sum += mm + logf(ss);
    }

    if (tid == 0) {
        double vkb = (double)lse_sum / (double)R_ - (double)pos;   // >= 0
        long long q = __double2ll_rn(vkb * 4294967296.0);
        atomicAdd(&g_acc, (unsigned long long)q);
        __threadfence();
        if (atomicAdd(&g_cnt, 1) == K_ * B_ - 1) {
            unsigned long long tot = atomicAdd(&g_acc, 0ULL);
            out[0] = (float)((double)(long long)tot / 4294967296.0
                             / (double)(K_ * B_));
        }
    }
}

// ============================================================================
extern "C" void kernel_launch(void* const* d_in, const int* in_sizes, int n_in,
                              void* d_out, int out_size) {
    const float* z        = (const float*)d_in[0];
    const float* c        = (const float*)d_in[1];
    const float* Wk_w     = (const float*)d_in[2];
    const float* Wk_b     = (const float*)d_in[3];
    const int*   t        = (const int*)d_in[4];
    const int*   rand_idx = (const int*)d_in[5];

    cudaFuncSetAttribute(score_kernel,
                         cudaFuncAttributeMaxDynamicSharedMemorySize, SCORE_SMEM);

    pred_kernel<<<KO_ / 64, 256>>>(c, Wk_w, Wk_b, t);
    score_kernel<<<dim3(T_ / RPB, B_), 128, SCORE_SMEM>>>(z);
    loss_kernel<<<K_ * B_, 256>>>(t, rand_idx, (float*)d_out);
}

// round 3
// speedup vs baseline: 1.4198x; 1.3424x over previous
#include <cuda_runtime.h>
#include <cstdint>

#define B_   64
#define T_   2048
#define DZ_  512
#define DC_  256
#define K_   12
#define R_   2
#define KO_  (K_ * DZ_)     // 6144

// score kernel tiling
#define RPB  512            // t' rows per block
#define SDK  16             // d floats per pipeline stage
#define NSTG (DZ_ / SDK)    // 32 stages
#define PF4  5              // smem row pitch in float4 (80 B -> conflict-free LDS.128)
#define STAGE_F4 (RPB * PF4)
#define SCORE_SMEM (KO_ * 4 + 2 * STAGE_F4 * 16)   // 24576 + 81920 = 106496 B

#define PRED_SMEM (2 * DC_ * 64 * 4)               // 131072 B (cts_t + ws_t)

// ---- scratch (static device allocations; no cudaMalloc allowed) ----
__device__ __align__(16) float g_pred[B_ * KO_];   // [b][k*Dz+o]
__device__ __align__(16) float g_s[K_ * B_ * T_];  // [k][b][t']
__device__ unsigned long long g_acc;               // Q32.32 fixed-point loss accum
__device__ int g_cnt;

extern __shared__ __align__(16) float smem_dyn[];

static __device__ __forceinline__ unsigned smem_u32(const void* p) {
    return (unsigned)__cvta_generic_to_shared(p);
}
static __device__ __forceinline__ unsigned long long dup32(float x) {
    unsigned long long r;
    asm("mov.b64 %0, {%1, %1};" : "=l"(r) : "r"(__float_as_uint(x)));
    return r;
}
// d-major smem index with 16B-chunk XOR swizzle: conflict-free LDS.128 reads
static __device__ __forceinline__ int swz(int d, int r) {
    return d * 64 + ((((r >> 2) ^ ((d >> 2) & 15)) << 2) | (r & 3));
}

// ============================================================================
// Kernel A: pred[b][ko] = sum_d c[b, t[b], d] * W[ko][d] + bias[ko]
// GEMM 64 x 6144 x 256; d-major swizzled smem, f32x2 over ko-pairs.
// grid = 96 blocks (64 ko each), 256 threads = 16(ko)x16(b), micro 4x4.
// ============================================================================
__global__ __launch_bounds__(256) void pred_kernel(const float* __restrict__ c,
                                                   const float* __restrict__ W,
                                                   const float* __restrict__ bias,
                                                   const int*   __restrict__ t) {
    float* cts = smem_dyn;                 // [256 d][64 b] swizzled
    float* ws  = smem_dyn + DC_ * 64;      // [256 d][64 ko] swizzled
    __shared__ int ts[B_];

    int tid = threadIdx.x;
    if (blockIdx.x == 0 && tid == 0) { g_acc = 0ULL; g_cnt = 0; }
    if (tid < B_) ts[tid] = t[tid];
    __syncthreads();

    int ko0 = blockIdx.x * 64;

    // single-phase load+transpose: 16 float4 per thread per matrix
    #pragma unroll
    for (int i = 0; i < 16; i++) {
        int f  = tid + i * 256;
        int r  = f >> 6, c4 = f & 63, d0 = c4 * 4;
        float4 v = *(const float4*)(c + ((long)r * T_ + ts[r]) * DC_ + d0);
        cts[swz(d0 + 0, r)] = v.x;  cts[swz(d0 + 1, r)] = v.y;
        cts[swz(d0 + 2, r)] = v.z;  cts[swz(d0 + 3, r)] = v.w;
        float4 wv = *(const float4*)(W + (long)(ko0 + r) * DC_ + d0);
        ws[swz(d0 + 0, r)] = wv.x;  ws[swz(d0 + 1, r)] = wv.y;
        ws[swz(d0 + 2, r)] = wv.z;  ws[swz(d0 + 3, r)] = wv.w;
    }
    __syncthreads();

    int tx = tid & 15, ty = tid >> 4;
    unsigned long long acc[4][2];          // [b_i][ko pair] f32x2
    #pragma unroll
    for (int i = 0; i < 4; i++) { acc[i][0] = 0ULL; acc[i][1] = 0ULL; }

    #pragma unroll 4
    for (int d = 0; d < DC_; d++) {
        int sw = (d >> 2) & 15;
        float4 cv = *(const float4*)(cts + d * 64 + ((ty ^ sw) << 2));
        ulonglong2 wp = *(const ulonglong2*)(ws + d * 64 + ((tx ^ sw) << 2));
        unsigned long long cd[4] = { dup32(cv.x), dup32(cv.y), dup32(cv.z), dup32(cv.w) };
        #pragma unroll
        for (int i = 0; i < 4; i++) {
            asm("fma.rn.f32x2 %0, %1, %2, %0;" : "+l"(acc[i][0]) : "l"(cd[i]), "l"(wp.x));
            asm("fma.rn.f32x2 %0, %1, %2, %0;" : "+l"(acc[i][1]) : "l"(cd[i]), "l"(wp.y));
        }
    }

    #pragma unroll
    for (int i = 0; i < 4; i++) {
        int b = ty * 4 + i;
        #pragma unroll
        for (int p = 0; p < 2; p++) {
            int ko = ko0 + tx * 4 + 2 * p;
            float lo = __uint_as_float((unsigned)(acc[i][p] & 0xffffffffu));
            float hi = __uint_as_float((unsigned)(acc[i][p] >> 32));
            g_pred[(long)b * KO_ + ko]     = lo + bias[ko];
            g_pred[(long)b * KO_ + ko + 1] = hi + bias[ko + 1];
        }
    }
}

// ============================================================================
// Kernel B (hot): s[k][b][t'] = dot(z[b,t',:], pred[b,k,:])
// z (268 MB) streamed once via 16B cp.async.cg double buffer, pitch-5-float4
// rows (conflict-free LDS.128). 4 rows/thread, FFMA2 accumulation.
// grid = (T/512, B) = 256 blocks, 128 threads, 2 blocks/SM.
// ============================================================================
__global__ __launch_bounds__(128) void score_kernel(const float* __restrict__ z) {
    float*  preds = smem_dyn;                        // 6144 floats
    float4* zbuf  = (float4*)(smem_dyn + KO_);       // 2 x (512*5) float4

    const int tid  = threadIdx.x;
    const int b    = blockIdx.y;
    const int t0   = blockIdx.x * RPB;
    const int l    = tid & 31, w = tid >> 5;
    const int base = w * 128;

    const float* zb = z + ((long)b * T_ + t0) * DZ_;

    auto load_stage = [&](int s, int bufsel) {
        unsigned sb = smem_u32(zbuf + bufsel * STAGE_F4);
        const float* gs = zb + s * SDK;
        #pragma unroll
        for (int j = 0; j < 16; j++) {
            int f = tid + j * 128;                   // 0..2047 float4 slots
            int r = f >> 2, cc = f & 3;
            unsigned sa = sb + (unsigned)((r * PF4 + cc) * 16);
            const float* ga = gs + (long)r * DZ_ + cc * 4;
            asm volatile("cp.async.cg.shared.global [%0], [%1], 16;\n"
                         :: "r"(sa), "l"(ga));
        }
        asm volatile("cp.async.commit_group;\n");
    };

    load_stage(0, 0);
    load_stage(1, 1);

    // stage this b's 12 pred vectors
    const float4* gp = (const float4*)(g_pred + (long)b * KO_);
    float4* sp = (float4*)preds;
    #pragma unroll
    for (int i = 0; i < KO_ / 4 / 128; i++) sp[tid + i * 128] = gp[tid + i * 128];

    unsigned long long acc[4][K_];
    #pragma unroll
    for (int i = 0; i < 4; i++)
        #pragma unroll
        for (int k = 0; k < K_; k++) acc[i][k] = 0ULL;

    for (int s = 0; s < NSTG; s++) {
        if (s < NSTG - 1) asm volatile("cp.async.wait_group 1;\n");
        else              asm volatile("cp.async.wait_group 0;\n");
        __syncthreads();

        const float4* zc = zbuf + (s & 1) * STAGE_F4;
        #pragma unroll
        for (int c4 = 0; c4 < 4; c4++) {
            ulonglong2 zz[4];
            #pragma unroll
            for (int i = 0; i < 4; i++)
                zz[i] = *(const ulonglong2*)(zc + (base + 32 * i + l) * PF4 + c4);
            #pragma unroll
            for (int k = 0; k < K_; k++) {
                ulonglong2 p = *(const ulonglong2*)(preds + k * DZ_ + s * SDK + c4 * 4);
                #pragma unroll
                for (int i = 0; i < 4; i++) {
                    asm("fma.rn.f32x2 %0, %1, %2, %0;"
                        : "+l"(acc[i][k]) : "l"(zz[i].x), "l"(p.x));
                    asm("fma.rn.f32x2 %0, %1, %2, %0;"
                        : "+l"(acc[i][k]) : "l"(zz[i].y), "l"(p.y));
                }
            }
        }
        __syncthreads();
        if (s + 2 < NSTG) load_stage(s + 2, s & 1);
    }

    #pragma unroll
    for (int i = 0; i < 4; i++) {
        int row = t0 + base + 32 * i + l;
        #pragma unroll
        for (int k = 0; k < K_; k++) {
            float lo = __uint_as_float((unsigned)(acc[i][k] & 0xffffffffu));
            float hi = __uint_as_float((unsigned)(acc[i][k] >> 32));
            g_s[((long)k * B_ + b) * T_ + row] = lo + hi;
        }
    }
}

// ============================================================================
// Kernel C: per (k,b): pos + 2 replicates of 2047 sampled negatives ->
// mean logsumexp. Q32.32 integer atomic finale (deterministic).
// grid = 768 blocks, 256 threads.
// ============================================================================
__global__ __launch_bounds__(256) void loss_kernel(const int* __restrict__ t,
                                                   const int* __restrict__ ridx_g,
                                                   float* __restrict__ out) {
    __shared__ float srow[T_];
    __shared__ float red[8];

    int tid = threadIdx.x;
    int kb  = blockIdx.x;
    int k = kb >> 6, b = kb & 63;           // kb = k*B + b
    int lane = tid & 31, wid = tid >> 5;

    const float* src = g_s + (long)kb * T_;
    for (int i = tid; i < T_; i += 256) srow[i] = src[i];
    __syncthreads();

    int e = t[b] + k + 1;
    float pos = srow[e];
    float lse_sum = 0.f;

    for (int r = 0; r < R_; r++) {
        const int* ridx = ridx_g + (k * R_ + r) * (T_ - 1);
        float v[8];
        float m = pos;
        #pragma unroll
        for (int it = 0; it < 8; it++) {
            int i = tid + it * 256;
            float x = -3.0e38f;
            if (i < T_ - 1) {
                int j = ridx[i];
                j += (j >= e);              // skip the positive frame
                x = srow[j];
            }
            v[it] = x;
            m = fmaxf(m, x);
        }
        #pragma unroll
        for (int o = 16; o; o >>= 1) m = fmaxf(m, __shfl_xor_sync(0xffffffffu, m, o));
        if (lane == 0) red[wid] = m;
        __syncthreads();
        float mm = red[0];
        #pragma unroll
        for (int j = 1; j < 8; j++) mm = fmaxf(mm, red[j]);
        __syncthreads();

        float sacc = (tid == 0) ? expf(pos - mm) : 0.f;
        #pragma unroll
        for (int it = 0; it < 8; it++)
            if (tid + it * 256 < T_ - 1) sacc += expf(v[it] - mm);
        #pragma unroll
        for (int o = 16; o; o >>= 1) sacc += __shfl_xor_sync(0xffffffffu, sacc, o);
        if (lane == 0) red[wid] = sacc;
        __syncthreads();
        float ss = red[0];
        #pragma unroll
        for (int j = 1; j < 8; j++) ss += red[j];
        __syncthreads();

        lse_sum += mm + logf(ss);
    }

    if (tid == 0) {
        double vkb = (double)lse_sum / (double)R_ - (double)pos;   // >= 0
        long long q = __double2ll_rn(vkb * 4294967296.0);
        atomicAdd(&g_acc, (unsigned long long)q);
        __threadfence();
        if (atomicAdd(&g_cnt, 1) == K_ * B_ - 1) {
            unsigned long long tot = atomicAdd(&g_acc, 0ULL);
            out[0] = (float)((double)(long long)tot / 4294967296.0
                             / (double)(K_ * B_));
        }
    }
}

// ============================================================================
extern "C" void kernel_launch(void* const* d_in, const int* in_sizes, int n_in,
                              void* d_out, int out_size) {
    const float* z        = (const float*)d_in[0];
    const float* c        = (const float*)d_in[1];
    const float* Wk_w     = (const float*)d_in[2];
    const float* Wk_b     = (const float*)d_in[3];
    const int*   t        = (const int*)d_in[4];
    const int*   rand_idx = (const int*)d_in[5];

    cudaFuncSetAttribute(pred_kernel,
                         cudaFuncAttributeMaxDynamicSharedMemorySize, PRED_SMEM);
    cudaFuncSetAttribute(score_kernel,
                         cudaFuncAttributeMaxDynamicSharedMemorySize, SCORE_SMEM);

    pred_kernel<<<KO_ / 64, 256, PRED_SMEM>>>(c, Wk_w, Wk_b, t);
    score_kernel<<<dim3(T_ / RPB, B_), 128, SCORE_SMEM>>>(z);
    loss_kernel<<<K_ * B_, 256>>>(t, rand_idx, (float*)d_out);
}